// round 1
// baseline (speedup 1.0000x reference)
#include <cuda_runtime.h>
#include <math.h>

// Problem constants (shapes fixed by setup_inputs)
#define M_ROWS   8192
#define N_NODES  255
#define K_DIM    2048
#define N_LEAVES 256
#define N_OUT    100
#define N_PEN    127    // 2^(D-1)-1 inner nodes used for penalty

// ---------------- scratch (device globals; no allocation allowed) ----------
__device__ float g_p[M_ROWS * N_NODES];       // sigmoid gate probs, heap order
__device__ float g_Q[N_LEAVES * N_OUT];       // softmax(leaf_params)
__device__ float g_logQT[N_OUT * N_LEAVES];   // log_softmax transposed [out][leaf]
__device__ float g_num[N_PEN * M_ROWS];       // p * inner_path, [node][row]
__device__ float g_den[N_PEN * M_ROWS];       // inner_path,     [node][row]
__device__ float g_rowloss[M_ROWS];
__device__ float g_cterm[N_PEN];

// ---------------- kernel 0: log-softmax of leaf params ---------------------
__global__ void softmax_kernel(const float* __restrict__ leaf_params) {
    int l = threadIdx.x;
    if (l >= N_LEAVES) return;
    const float* row = leaf_params + l * N_OUT;
    float mx = -INFINITY;
    #pragma unroll 4
    for (int o = 0; o < N_OUT; o++) mx = fmaxf(mx, row[o]);
    float s = 0.f;
    #pragma unroll 4
    for (int o = 0; o < N_OUT; o++) s += expf(row[o] - mx);
    float lse = mx + logf(s);
    for (int o = 0; o < N_OUT; o++) {
        float lq = row[o] - lse;
        g_Q[l * N_OUT + o]      = expf(lq);
        g_logQT[o * N_LEAVES + l] = lq;
    }
}

// ---------------- kernel A: tiled SGEMM + bias + beta + sigmoid ------------
// p[i][j] = sigmoid(beta[j] * (dot(x[i,:], W[j,:]) + b[j]))
#define BM 64
#define BN 64
#define BK 16

__global__ __launch_bounds__(256) void gemm_sigmoid_kernel(
    const float* __restrict__ X, const float* __restrict__ W,
    const float* __restrict__ bias, const float* __restrict__ beta)
{
    __shared__ float As[BK][BM];
    __shared__ float Bs[BK][BN];

    const int tid = threadIdx.x;          // 256 threads
    const int bm  = blockIdx.x * BM;
    const int bn  = blockIdx.y * BN;

    // loader mapping: 256 threads x float4 = 1024 floats = one 64x16 tile
    const int lr = tid >> 2;              // 0..63 row within tile
    const int lc = (tid & 3) * 4;         // 0,4,8,12 within K-slab

    // compute mapping: 16x16 threads, each computes a 4x4 micro-tile
    const int tx = tid & 15;
    const int ty = tid >> 4;

    float acc[4][4];
    #pragma unroll
    for (int i = 0; i < 4; i++)
        #pragma unroll
        for (int j = 0; j < 4; j++) acc[i][j] = 0.f;

    for (int k0 = 0; k0 < K_DIM; k0 += BK) {
        // load A tile (M always in range: 8192 % 64 == 0)
        float4 a4 = *(const float4*)(X + (size_t)(bm + lr) * K_DIM + k0 + lc);
        As[lc + 0][lr] = a4.x; As[lc + 1][lr] = a4.y;
        As[lc + 2][lr] = a4.z; As[lc + 3][lr] = a4.w;

        // load B tile (W rows may exceed 254 on last block)
        int wr = bn + lr;
        float4 b4 = make_float4(0.f, 0.f, 0.f, 0.f);
        if (wr < N_NODES)
            b4 = *(const float4*)(W + (size_t)wr * K_DIM + k0 + lc);
        Bs[lc + 0][lr] = b4.x; Bs[lc + 1][lr] = b4.y;
        Bs[lc + 2][lr] = b4.z; Bs[lc + 3][lr] = b4.w;

        __syncthreads();

        #pragma unroll
        for (int kk = 0; kk < BK; kk++) {
            float4 ra = *(const float4*)&As[kk][ty * 4];
            float4 rb = *(const float4*)&Bs[kk][tx * 4];
            float a[4] = {ra.x, ra.y, ra.z, ra.w};
            float b[4] = {rb.x, rb.y, rb.z, rb.w};
            #pragma unroll
            for (int i = 0; i < 4; i++)
                #pragma unroll
                for (int j = 0; j < 4; j++)
                    acc[i][j] = fmaf(a[i], b[j], acc[i][j]);
        }
        __syncthreads();
    }

    // epilogue: bias, beta scale, sigmoid
    #pragma unroll
    for (int j = 0; j < 4; j++) {
        int col = bn + tx * 4 + j;
        if (col >= N_NODES) continue;
        float bj  = bias[col];
        float btj = beta[col];
        #pragma unroll
        for (int i = 0; i < 4; i++) {
            int row = bm + ty * 4 + i;
            float z = btj * (acc[i][j] + bj);
            g_p[(size_t)row * N_NODES + col] = 1.f / (1.f + expf(-z));
        }
    }
}

// ---------------- kernel B: per-row tree paths ------------------------------
// One block per batch row, 256 threads (one per leaf / node).
__global__ __launch_bounds__(256) void tree_kernel(
    const int* __restrict__ labels, float* __restrict__ out_output)
{
    const int i = blockIdx.x;
    const int t = threadIdx.x;

    __shared__ float sp[256];      // gate probs for this row
    __shared__ float red[256];
    __shared__ int   redi[256];
    __shared__ int   s_label;

    sp[t] = (t < N_NODES) ? g_p[(size_t)i * N_NODES + t] : 0.f;
    if (t == 0) s_label = labels[i];
    __syncthreads();
    const int label = s_label;

    // leaf path: leaf t corresponds to 1-based heap index m = 256 + t.
    // Walk bits of m below the MSB; bit==1 -> right child -> factor p.
    unsigned m = 256u + (unsigned)t;
    float lp = 1.f;
    #pragma unroll
    for (int k = 7; k >= 0; --k) {
        unsigned a  = m >> (k + 1);        // 1-based ancestor
        unsigned bt = (m >> k) & 1u;
        float pa = sp[a - 1];
        lp *= bt ? pa : (1.f - pa);
    }
    float leafval = lp;
    float lossv = leafval * g_logQT[label * N_LEAVES + t];

    // inner path + alpha partials for penalized nodes (t < 127)
    if (t < N_PEN) {
        unsigned m2 = (unsigned)t + 1u;
        int nb = 31 - __clz((int)m2);      // bits below MSB
        float iv = 1.f;
        for (int k = nb - 1; k >= 0; --k) {
            unsigned a  = m2 >> (k + 1);
            unsigned bt = (m2 >> k) & 1u;
            float pa = sp[a - 1];
            iv *= bt ? pa : (1.f - pa);
        }
        g_num[(size_t)t * M_ROWS + i] = sp[t] * iv;
        g_den[(size_t)t * M_ROWS + i] = iv;
    }

    // deterministic tree-reduce of loss contribution
    red[t] = lossv;
    __syncthreads();
    #pragma unroll
    for (int s = 128; s > 0; s >>= 1) {
        if (t < s) red[t] += red[t + s];
        __syncthreads();
    }
    if (t == 0) g_rowloss[i] = red[0];
    __syncthreads();

    // argmax over leaf path (first-max tie break, like jnp.argmax)
    red[t]  = leafval;
    redi[t] = t;
    __syncthreads();
    #pragma unroll
    for (int s = 128; s > 0; s >>= 1) {
        if (t < s) {
            float v2 = red[t + s]; int i2 = redi[t + s];
            if (v2 > red[t] || (v2 == red[t] && i2 < redi[t])) {
                red[t] = v2; redi[t] = i2;
            }
        }
        __syncthreads();
    }
    const int best = redi[0];

    // output row = Q[best_leaf]
    if (t < N_OUT)
        out_output[(size_t)i * N_OUT + t] = g_Q[best * N_OUT + t];
}

// ---------------- kernel C: column reductions (alpha terms + loss) ---------
__global__ __launch_bounds__(256) void reduce_kernel(float* __restrict__ out)
{
    const int j = blockIdx.x;   // 0..126 nodes, 127 = loss
    const int t = threadIdx.x;
    __shared__ float s1[256];
    __shared__ float s2[256];

    if (j < N_PEN) {
        const float* num = g_num + (size_t)j * M_ROWS;
        const float* den = g_den + (size_t)j * M_ROWS;
        float a = 0.f, d = 0.f;
        for (int r = t; r < M_ROWS; r += 256) { a += num[r]; d += den[r]; }
        s1[t] = a; s2[t] = d;
        __syncthreads();
        #pragma unroll
        for (int s = 128; s > 0; s >>= 1) {
            if (t < s) { s1[t] += s1[t + s]; s2[t] += s2[t + s]; }
            __syncthreads();
        }
        if (t == 0) {
            float alpha = s1[0] / s2[0];
            int depth = 32 - __clz(j + 1);           // floor(log2(j+1)) + 1
            float lm = 0.1f * exp2f(-(float)depth);
            g_cterm[j] = lm * 0.5f * (logf(alpha) + log1pf(-alpha));
        }
    } else {
        float a = 0.f;
        for (int r = t; r < M_ROWS; r += 256) a += g_rowloss[r];
        s1[t] = a;
        __syncthreads();
        #pragma unroll
        for (int s = 128; s > 0; s >>= 1) {
            if (t < s) s1[t] += s1[t + s];
            __syncthreads();
        }
        if (t == 0) out[0] = -(s1[0] / (float)M_ROWS);   // neg_loss
    }
}

// ---------------- kernel D: final C scalar ----------------------------------
__global__ void cfinal_kernel(float* __restrict__ out)
{
    const int t = threadIdx.x;  // 128
    __shared__ float s1[128];
    s1[t] = (t < N_PEN) ? g_cterm[t] : 0.f;
    __syncthreads();
    #pragma unroll
    for (int s = 64; s > 0; s >>= 1) {
        if (t < s) s1[t] += s1[t + s];
        __syncthreads();
    }
    if (t == 0) out[1 + M_ROWS * N_OUT] = -s1[0];        // C
}

// ---------------- entry -----------------------------------------------------
extern "C" void kernel_launch(void* const* d_in, const int* in_sizes, int n_in,
                              void* d_out, int out_size)
{
    const float* x           = (const float*)d_in[0];
    const int*   labels      = (const int*)  d_in[1];
    const float* W           = (const float*)d_in[2];
    const float* b           = (const float*)d_in[3];
    const float* beta        = (const float*)d_in[4];
    const float* leaf_params = (const float*)d_in[5];
    float* out = (float*)d_out;

    // 0) softmax / log-softmax of leaf params
    softmax_kernel<<<1, 256>>>(leaf_params);

    // A) gate probabilities p = sigmoid(beta*(x@W.T + b))
    dim3 grid(M_ROWS / BM, (N_NODES + BN - 1) / BN);
    gemm_sigmoid_kernel<<<grid, 256>>>(x, W, b, beta);

    // B) per-row tree paths, loss partials, alpha partials, output rows
    tree_kernel<<<M_ROWS, 256>>>(labels, out + 1);

    // C) reductions: alpha -> cterm, loss -> out[0]
    reduce_kernel<<<N_PEN + 1, 256>>>(out);

    // D) final C scalar
    cfinal_kernel<<<1, 128>>>(out);
}

// round 3
// speedup vs baseline: 2.4968x; 2.4968x over previous
#include <cuda_runtime.h>
#include <cuda_bf16.h>
#include <math.h>
#include <stdint.h>

// Problem constants (shapes fixed by setup_inputs)
#define M_ROWS   8192
#define N_NODES  255
#define K_DIM    2048
#define N_LEAVES 256
#define N_OUT    100
#define N_PEN    127

// GEMM tiling: CTA 128x128, BK=32, 8 warps of 64x32
#define BM 128
#define BN 128
#define BK 32
#define NKCHUNK (K_DIM / BK)       // 64
#define SSTRIDE 36                 // bf16 elements per smem row (32 + 4 pad) = 72 B
#define TILE_BYTES (BM * SSTRIDE * 2)        // 9216 B per tile
#define STAGE_BYTES (4 * TILE_BYTES)         // Ahi,Alo,Bhi,Blo = 36864 B
#define DYN_BYTES (2 * STAGE_BYTES)          // double buffered = 73728 B

// ---------------- scratch (device globals; no allocation allowed) ----------
__device__ float g_p[M_ROWS * 256];           // gate probs, stride 256
__device__ float g_Q[N_LEAVES * N_OUT];
__device__ float g_logQT[N_OUT * N_LEAVES];
__device__ float g_num[N_PEN * M_ROWS];
__device__ float g_den[N_PEN * M_ROWS];
__device__ float g_rowloss[M_ROWS];
__device__ float g_cterm[N_PEN];

// ---------------- mma helper -------------------------------------------------
__device__ __forceinline__ void mma16816(float* c, const uint32_t* a, const uint32_t* b) {
    asm volatile(
        "mma.sync.aligned.m16n8k16.row.col.f32.bf16.bf16.f32 "
        "{%0,%1,%2,%3}, {%4,%5,%6,%7}, {%8,%9}, {%0,%1,%2,%3};"
        : "+f"(c[0]), "+f"(c[1]), "+f"(c[2]), "+f"(c[3])
        : "r"(a[0]), "r"(a[1]), "r"(a[2]), "r"(a[3]), "r"(b[0]), "r"(b[1]));
}

// split 4 fp32 -> bf16 hi pair-regs + lo pair-regs
__device__ __forceinline__ void cvt_split4(float4 v, uint32_t* h, uint32_t* l) {
    __nv_bfloat162 h01 = __float22bfloat162_rn(make_float2(v.x, v.y));
    __nv_bfloat162 h23 = __float22bfloat162_rn(make_float2(v.z, v.w));
    float rx = v.x - __bfloat162float(h01.x);
    float ry = v.y - __bfloat162float(h01.y);
    float rz = v.z - __bfloat162float(h23.x);
    float rw = v.w - __bfloat162float(h23.y);
    __nv_bfloat162 l01 = __float22bfloat162_rn(make_float2(rx, ry));
    __nv_bfloat162 l23 = __float22bfloat162_rn(make_float2(rz, rw));
    h[0] = *(uint32_t*)&h01; h[1] = *(uint32_t*)&h23;
    l[0] = *(uint32_t*)&l01; l[1] = *(uint32_t*)&l23;
}

// ---------------- kernel 0: log-softmax of leaf params ---------------------
__global__ void softmax_kernel(const float* __restrict__ leaf_params) {
    int l = threadIdx.x;
    if (l >= N_LEAVES) return;
    const float* row = leaf_params + l * N_OUT;
    float mx = -INFINITY;
    for (int o = 0; o < N_OUT; o++) mx = fmaxf(mx, row[o]);
    float s = 0.f;
    for (int o = 0; o < N_OUT; o++) s += expf(row[o] - mx);
    float lse = mx + logf(s);
    for (int o = 0; o < N_OUT; o++) {
        float lq = row[o] - lse;
        g_Q[l * N_OUT + o]        = expf(lq);
        g_logQT[o * N_LEAVES + l] = lq;
    }
}

// ---------------- kernel A: bf16-split HMMA GEMM + sigmoid -----------------
// p[i][j] = sigmoid(beta[j] * (dot(x[i,:], W[j,:]) + b[j]))
__global__ __launch_bounds__(256, 1) void gemm_mma_kernel(
    const float* __restrict__ X, const float* __restrict__ W,
    const float* __restrict__ bias_g, const float* __restrict__ beta_g)
{
    extern __shared__ __align__(16) char dyn[];
    __shared__ float s_beta[BN], s_bias[BN];

    const int tid  = threadIdx.x;
    const int wid  = tid >> 5;
    const int lane = tid & 31;
    const int m_base = blockIdx.x * BM;
    const int bn     = blockIdx.y * BN;

    // preload beta/bias for this N block
    if (tid < BN) {
        int col = bn + tid;
        float bt = 0.f, bs = 0.f;
        if (col < N_NODES) { bt = beta_g[col]; bs = bias_g[col]; }
        s_beta[tid] = bt; s_bias[tid] = bs;
    }

    // smem tile pointers (bf16, row stride SSTRIDE elements)
    __nv_bfloat16* smb = (__nv_bfloat16*)dyn;
    const int TILE_ELEMS = BM * SSTRIDE;

    // loader mapping: idx = tid + it*256; row = idx>>3, c4 = idx&7 (float4 col)
    const int lr  = tid >> 3;          // base row (stride 32 over iters)
    const int lc4 = tid & 7;           // float4 index within 32-float row

    // compute mapping
    const int wm = wid & 1;            // 0..1  -> 64-row slab
    const int wn = wid >> 1;           // 0..3  -> 32-col slab
    const int g   = lane >> 2;         // group id 0..7
    const int tig = lane & 3;          // thread in group

    float acc[4][4][4];
    #pragma unroll
    for (int mi = 0; mi < 4; mi++)
        #pragma unroll
        for (int ni = 0; ni < 4; ni++)
            #pragma unroll
            for (int r = 0; r < 4; r++) acc[mi][ni][r] = 0.f;

    // prefetch chunk 0 into registers
    float4 aregs[4], bregs[4];
    {
        const int k0 = 0;
        #pragma unroll
        for (int it = 0; it < 4; it++) {
            int r = lr + it * 32;
            aregs[it] = *(const float4*)(X + (size_t)(m_base + r) * K_DIM + k0 + lc4 * 4);
            int nrow = bn + r;
            float4 bv = make_float4(0.f, 0.f, 0.f, 0.f);
            if (nrow < N_NODES)
                bv = *(const float4*)(W + (size_t)nrow * K_DIM + k0 + lc4 * 4);
            bregs[it] = bv;
        }
    }

    for (int kc = 0; kc < NKCHUNK; kc++) {
        const int buf = kc & 1;
        __nv_bfloat16* Ahi = smb + buf * (4 * TILE_ELEMS);
        __nv_bfloat16* Alo = Ahi + TILE_ELEMS;
        __nv_bfloat16* Bhi = Alo + TILE_ELEMS;
        __nv_bfloat16* Blo = Bhi + TILE_ELEMS;

        // convert + store prefetched regs to smem
        #pragma unroll
        for (int it = 0; it < 4; it++) {
            int r = lr + it * 32;
            uint32_t h[2], l[2];
            cvt_split4(aregs[it], h, l);
            uint32_t* dsth = (uint32_t*)(Ahi + r * SSTRIDE + lc4 * 4);
            uint32_t* dstl = (uint32_t*)(Alo + r * SSTRIDE + lc4 * 4);
            dsth[0] = h[0]; dsth[1] = h[1];
            dstl[0] = l[0]; dstl[1] = l[1];
            cvt_split4(bregs[it], h, l);
            dsth = (uint32_t*)(Bhi + r * SSTRIDE + lc4 * 4);
            dstl = (uint32_t*)(Blo + r * SSTRIDE + lc4 * 4);
            dsth[0] = h[0]; dsth[1] = h[1];
            dstl[0] = l[0]; dstl[1] = l[1];
        }
        __syncthreads();

        // prefetch next chunk
        if (kc + 1 < NKCHUNK) {
            const int k0 = (kc + 1) * BK;
            #pragma unroll
            for (int it = 0; it < 4; it++) {
                int r = lr + it * 32;
                aregs[it] = *(const float4*)(X + (size_t)(m_base + r) * K_DIM + k0 + lc4 * 4);
                int nrow = bn + r;
                float4 bv = make_float4(0.f, 0.f, 0.f, 0.f);
                if (nrow < N_NODES)
                    bv = *(const float4*)(W + (size_t)nrow * K_DIM + k0 + lc4 * 4);
                bregs[it] = bv;
            }
        }

        // compute: two ksteps of 16 within this BK=32 chunk
        #pragma unroll
        for (int kk = 0; kk < 2; kk++) {
            const int kb = kk * 16;        // element offset within chunk
            uint32_t ah[4][4], al[4][4], bh[4][2], bl[4][2];
            #pragma unroll
            for (int mi = 0; mi < 4; mi++) {
                int r0 = wm * 64 + mi * 16 + g;
                const uint32_t* ph0 = (const uint32_t*)(Ahi + r0 * SSTRIDE + kb + 2 * tig);
                const uint32_t* ph1 = (const uint32_t*)(Ahi + (r0 + 8) * SSTRIDE + kb + 2 * tig);
                const uint32_t* pl0 = (const uint32_t*)(Alo + r0 * SSTRIDE + kb + 2 * tig);
                const uint32_t* pl1 = (const uint32_t*)(Alo + (r0 + 8) * SSTRIDE + kb + 2 * tig);
                ah[mi][0] = ph0[0]; ah[mi][1] = ph1[0]; ah[mi][2] = ph0[4]; ah[mi][3] = ph1[4];
                al[mi][0] = pl0[0]; al[mi][1] = pl1[0]; al[mi][2] = pl0[4]; al[mi][3] = pl1[4];
            }
            #pragma unroll
            for (int ni = 0; ni < 4; ni++) {
                int n0 = wn * 32 + ni * 8 + g;
                const uint32_t* qh = (const uint32_t*)(Bhi + n0 * SSTRIDE + kb + 2 * tig);
                const uint32_t* ql = (const uint32_t*)(Blo + n0 * SSTRIDE + kb + 2 * tig);
                bh[ni][0] = qh[0]; bh[ni][1] = qh[4];
                bl[ni][0] = ql[0]; bl[ni][1] = ql[4];
            }
            #pragma unroll
            for (int mi = 0; mi < 4; mi++)
                #pragma unroll
                for (int ni = 0; ni < 4; ni++) {
                    mma16816(acc[mi][ni], ah[mi], bh[ni]);
                    mma16816(acc[mi][ni], ah[mi], bl[ni]);
                    mma16816(acc[mi][ni], al[mi], bh[ni]);
                }
        }
        __syncthreads();
    }

    // epilogue: sigmoid(beta*(acc+bias)) -> g_p
    #pragma unroll
    for (int mi = 0; mi < 4; mi++) {
        #pragma unroll
        for (int ni = 0; ni < 4; ni++) {
            int rloc = wm * 64 + mi * 16 + g;
            int cloc = wn * 32 + ni * 8 + 2 * tig;
            float bt0 = s_beta[cloc],     bs0 = s_bias[cloc];
            float bt1 = s_beta[cloc + 1], bs1 = s_bias[cloc + 1];
            float z0 = bt0 * (acc[mi][ni][0] + bs0);
            float z1 = bt1 * (acc[mi][ni][1] + bs1);
            float z2 = bt0 * (acc[mi][ni][2] + bs0);
            float z3 = bt1 * (acc[mi][ni][3] + bs1);
            float2 v0 = make_float2(1.f / (1.f + expf(-z0)), 1.f / (1.f + expf(-z1)));
            float2 v1 = make_float2(1.f / (1.f + expf(-z2)), 1.f / (1.f + expf(-z3)));
            size_t base0 = (size_t)(m_base + rloc) * 256 + bn + cloc;
            size_t base1 = (size_t)(m_base + rloc + 8) * 256 + bn + cloc;
            *(float2*)(g_p + base0) = v0;
            *(float2*)(g_p + base1) = v1;
        }
    }
}

// ---------------- kernel B: warp-per-row tree paths -------------------------
__global__ __launch_bounds__(256) void tree_kernel(
    const int* __restrict__ labels, float* __restrict__ out_output)
{
    __shared__ float sp[8][256];
    __shared__ float snum[N_PEN][8];
    __shared__ float sden[N_PEN][8];

    const int tid  = threadIdx.x;
    const int w    = tid >> 5;
    const int lane = tid & 31;
    const int i0   = blockIdx.x * 8;
    const int i    = i0 + w;

    float* spw = sp[w];
    const float* prow = g_p + (size_t)i * 256;
    #pragma unroll
    for (int j = 0; j < 8; j++) {
        int t = lane + j * 32;
        spw[t] = (t < N_NODES) ? prow[t] : 0.f;
    }
    __syncwarp();

    const int label = labels[i];

    float loss = 0.f;
    float best = -1.f;
    int   besti = 0;
    #pragma unroll
    for (int j = 0; j < 8; j++) {
        int t = j * 32 + lane;
        unsigned m = 256u + (unsigned)t;
        float lp = 1.f;
        #pragma unroll
        for (int k = 7; k >= 0; --k) {
            unsigned a  = m >> (k + 1);
            float pa = spw[a - 1];
            lp *= ((m >> k) & 1u) ? pa : (1.f - pa);
        }
        loss += lp * g_logQT[label * N_LEAVES + t];
        if (lp > best) { best = lp; besti = t; }
    }

    #pragma unroll
    for (int o = 16; o > 0; o >>= 1) {
        float v2 = __shfl_xor_sync(0xFFFFFFFFu, best, o);
        int   i2 = __shfl_xor_sync(0xFFFFFFFFu, besti, o);
        if (v2 > best || (v2 == best && i2 < besti)) { best = v2; besti = i2; }
        loss += __shfl_xor_sync(0xFFFFFFFFu, loss, o);
    }
    if (lane == 0) g_rowloss[i] = loss;

    #pragma unroll
    for (int j = 0; j < 4; j++) {
        int t = j * 32 + lane;
        if (t < N_PEN) {
            unsigned m2 = (unsigned)t + 1u;
            int nb = 31 - __clz((int)m2);
            float iv = 1.f;
            for (int k = nb - 1; k >= 0; --k) {
                unsigned a = m2 >> (k + 1);
                float pa = spw[a - 1];
                iv *= ((m2 >> k) & 1u) ? pa : (1.f - pa);
            }
            snum[t][w] = spw[t] * iv;
            sden[t][w] = iv;
        }
    }

    for (int o = lane; o < N_OUT; o += 32)
        out_output[(size_t)i * N_OUT + o] = g_Q[besti * N_OUT + o];

    __syncthreads();
    for (int idx = tid; idx < N_PEN * 8; idx += 256) {
        int t = idx >> 3, r = idx & 7;
        g_num[(size_t)t * M_ROWS + i0 + r] = snum[t][r];
        g_den[(size_t)t * M_ROWS + i0 + r] = sden[t][r];
    }
}

// ---------------- kernel C: column reductions (alpha terms + loss) ---------
__global__ __launch_bounds__(256) void reduce_kernel(float* __restrict__ out)
{
    const int j = blockIdx.x;
    const int t = threadIdx.x;
    __shared__ float s1[256];
    __shared__ float s2[256];

    if (j < N_PEN) {
        const float* num = g_num + (size_t)j * M_ROWS;
        const float* den = g_den + (size_t)j * M_ROWS;
        float a = 0.f, d = 0.f;
        for (int r = t; r < M_ROWS; r += 256) { a += num[r]; d += den[r]; }
        s1[t] = a; s2[t] = d;
        __syncthreads();
        #pragma unroll
        for (int s = 128; s > 0; s >>= 1) {
            if (t < s) { s1[t] += s1[t + s]; s2[t] += s2[t + s]; }
            __syncthreads();
        }
        if (t == 0) {
            float alpha = s1[0] / s2[0];
            int depth = 32 - __clz(j + 1);
            float lm = 0.1f * exp2f(-(float)depth);
            g_cterm[j] = lm * 0.5f * (logf(alpha) + log1pf(-alpha));
        }
    } else {
        float a = 0.f;
        for (int r = t; r < M_ROWS; r += 256) a += g_rowloss[r];
        s1[t] = a;
        __syncthreads();
        #pragma unroll
        for (int s = 128; s > 0; s >>= 1) {
            if (t < s) s1[t] += s1[t + s];
            __syncthreads();
        }
        if (t == 0) out[0] = -(s1[0] / (float)M_ROWS);
    }
}

// ---------------- kernel D: final C scalar ----------------------------------
__global__ void cfinal_kernel(float* __restrict__ out)
{
    const int t = threadIdx.x;  // 128
    __shared__ float s1[128];
    s1[t] = (t < N_PEN) ? g_cterm[t] : 0.f;
    __syncthreads();
    #pragma unroll
    for (int s = 64; s > 0; s >>= 1) {
        if (t < s) s1[t] += s1[t + s];
        __syncthreads();
    }
    if (t == 0) out[1 + M_ROWS * N_OUT] = -s1[0];
}

// ---------------- entry -----------------------------------------------------
extern "C" void kernel_launch(void* const* d_in, const int* in_sizes, int n_in,
                              void* d_out, int out_size)
{
    const float* x           = (const float*)d_in[0];
    const int*   labels      = (const int*)  d_in[1];
    const float* W           = (const float*)d_in[2];
    const float* b           = (const float*)d_in[3];
    const float* beta        = (const float*)d_in[4];
    const float* leaf_params = (const float*)d_in[5];
    float* out = (float*)d_out;

    cudaFuncSetAttribute(gemm_mma_kernel,
                         cudaFuncAttributeMaxDynamicSharedMemorySize, DYN_BYTES);

    softmax_kernel<<<1, 256>>>(leaf_params);
    dim3 grid(M_ROWS / BM, 256 / BN);
    gemm_mma_kernel<<<grid, 256, DYN_BYTES>>>(x, W, b, beta);
    tree_kernel<<<M_ROWS / 8, 256>>>(labels, out + 1);
    reduce_kernel<<<N_PEN + 1, 256>>>(out);
    cfinal_kernel<<<1, 128>>>(out);
}